// round 7
// baseline (speedup 1.0000x reference)
#include <cuda_runtime.h>

#define D     128
#define NMAX  50000
#define EMAX  800000
#define GIN_EPS 0.1f

// ---------------- device-resident configuration ----------------
struct Cfg {
    unsigned long long x;      // node features
    unsigned long long ei;     // edge_index
    unsigned long long ew;     // edge_weight
    unsigned long long w[4];   // W1a, W1b, W2a, W2b
    int E;
    int is64;
};
__device__ Cfg g_cfg;

__device__ __align__(16) float g_bufA[(size_t)NMAX * D];   // z accumulator
__device__ __align__(16) float g_bufB[(size_t)NMAX * D];   // h after layer 1

struct KArgs {
    unsigned long long p[12];
    long long          sz[12];
    int n_in;
    int N;
};

// ---------------- config kernel: classify inputs BY CONTENT ----------------
__global__ void k_config(KArgs a) {
    if (blockIdx.x != 0 || threadIdx.x != 0) return;
    Cfg c;
    bool used[12];
    for (int i = 0; i < 12; i++) used[i] = (i >= a.n_in);

    // 1) weights: exactly 16384 elements, taken in index order
    int nw = 0;
    for (int i = 0; i < a.n_in; i++)
        if (!used[i] && a.sz[i] == 16384 && nw < 4) { c.w[nw++] = a.p[i]; used[i] = true; }
    while (nw < 4) c.w[nw++] = a.p[0];   // degenerate fallback (shouldn't happen)

    // 2) x: size == N*128 AND samples look like N(0,1) (zeros/poison score ~0)
    long long xneed = (long long)a.N * 128;
    int xi = -1, best = -1;
    for (int i = 0; i < a.n_in; i++) {
        if (used[i] || a.sz[i] != xneed) continue;
        const float* f = (const float*)a.p[i];
        int sc = 0;
        for (int k = 0; k < 256; k++) {
            long long idx = (long long)k * (xneed - 1) / 255;
            float v = f[idx];
            if (isfinite(v) && fabsf(v) > 1e-6f && fabsf(v) < 1e4f) sc++;
        }
        if (sc > best) { best = sc; xi = i; }
    }
    if (xi < 0) {   // fallback: largest unused buffer
        long long b = -1;
        for (int i = 0; i < a.n_in; i++)
            if (!used[i] && a.sz[i] > b) { b = a.sz[i]; xi = i; }
        if (xi < 0) xi = 0;
    }
    c.x = a.p[xi]; used[xi] = true;

    // 3) edge_weight: remaining buffer with size in (0, EMAX], samples in [0,1]
    int ewi = -1; best = -1;
    for (int i = 0; i < a.n_in; i++) {
        if (used[i]) continue;
        long long s = a.sz[i];
        if (s < 1 || s > EMAX) continue;
        const float* f = (const float*)a.p[i];
        int sc = 0;
        for (int k = 0; k < 256; k++) {
            long long idx = (long long)k * (s - 1) / 255;
            float v = f[idx];
            if (isfinite(v) && v >= 0.0f && v <= 1.0f) sc++;
        }
        if (sc > best) { best = sc; ewi = i; }
    }
    if (ewi < 0) {
        long long b = (long long)1 << 62;
        for (int i = 0; i < a.n_in; i++)
            if (!used[i] && a.sz[i] < b) { b = a.sz[i]; ewi = i; }
        if (ewi < 0) ewi = 0;
    }
    c.ew = a.p[ewi]; used[ewi] = true;
    long long Ell = a.sz[ewi];
    c.E = (int)(Ell > EMAX ? EMAX : Ell);

    // 4) edge_index: remaining largest
    int eii = -1; long long b2 = -1;
    for (int i = 0; i < a.n_in; i++)
        if (!used[i] && a.sz[i] > b2) { b2 = a.sz[i]; eii = i; }
    if (eii < 0) eii = ewi;
    c.ei = a.p[eii];

    // 5) int64 vs int32: int64 indices < 2^31 have all odd 32-bit words == 0
    int is64 = 1;
    {
        const int* w32 = (const int*)c.ei;
        int samp = c.E < 2048 ? c.E : 2048;
        for (int k = 0; k < samp; k++)
            if (w32[2 * k + 1] != 0) { is64 = 0; break; }
    }
    c.is64 = is64;

    g_cfg = c;
}

// ---------------- zero-fill output ----------------
__global__ void k_zero_out(float* out, long long n) {
    long long i = (long long)blockIdx.x * blockDim.x + threadIdx.x;
    if (i < n) out[i] = 0.0f;
}

// ---------------- prep: bufA = (1+eps) * h ----------------
template <bool FIRST>
__global__ void k_prep(int n) {
    const float* h = FIRST ? (const float*)g_cfg.x : g_bufB;
    int i = blockIdx.x * blockDim.x + threadIdx.x;
    if (i < n * (D / 4)) {
        float4 v = ((const float4*)h)[i];
        v.x *= (1.0f + GIN_EPS);
        v.y *= (1.0f + GIN_EPS);
        v.z *= (1.0f + GIN_EPS);
        v.w *= (1.0f + GIN_EPS);
        ((float4*)g_bufA)[i] = v;
    }
}

// ---------------- scatter: bufA[dst] += w * h[src]  (one warp per edge) ----------------
template <bool FIRST>
__global__ void k_scatter(int n) {
    int t    = blockIdx.x * blockDim.x + threadIdx.x;
    int e    = t >> 5;
    int lane = t & 31;
    int E    = g_cfg.E;
    if (e >= E) return;

    int s, d;
    if (g_cfg.is64) {
        const long long* ii = (const long long*)g_cfg.ei;
        s = (int)ii[e];
        d = (int)ii[(size_t)E + e];
    } else {
        const int* ii = (const int*)g_cfg.ei;
        s = ii[e];
        d = ii[E + e];
    }
    if ((unsigned)s >= (unsigned)n || (unsigned)d >= (unsigned)n) return;

    const float* h = FIRST ? (const float*)g_cfg.x : g_bufB;
    float  w = ((const float*)g_cfg.ew)[e];
    float4 v = ((const float4*)(h + (size_t)s * D))[lane];
    float* dst = g_bufA + (size_t)d * D + lane * 4;
    atomicAdd(dst + 0, w * v.x);
    atomicAdd(dst + 1, w * v.y);
    atomicAdd(dst + 2, w * v.z);
    atomicAdd(dst + 3, w * v.w);
}

// ---------------- fused 2-layer MLP: Out = act2( relu(Z @ Wa) @ Wb ) ----------------
// 32 KB static smem; weights via __ldg (hot in L1). 256 thr = 8 warps;
// tile 32 rows x 128 cols; 4x4 micro-tile per thread.
template <int LAYER>
__global__ void k_mlp(float* __restrict__ OutExt, int n) {
    __shared__ __align__(16) float sZ[32 * 128];
    __shared__ __align__(16) float sT[32 * 128];

    const float* Wa = (const float*)(LAYER == 1 ? g_cfg.w[0] : g_cfg.w[2]);
    const float* Wb = (const float*)(LAYER == 1 ? g_cfg.w[1] : g_cfg.w[3]);

    const int tid  = threadIdx.x;
    const int row0 = blockIdx.x * 32;

    {
        float4* dz = (float4*)sZ;
        for (int i = tid; i < 1024; i += 256) {
            int r  = i >> 5;
            int cc = i & 31;
            int gr = row0 + r;
            float4 v = make_float4(0.f, 0.f, 0.f, 0.f);
            if (gr < n) v = ((const float4*)(g_bufA + (size_t)gr * D))[cc];
            dz[i] = v;
        }
    }
    __syncthreads();

    const int tx = tid & 31;
    const int ty = tid >> 5;

    float acc[4][4];
    #pragma unroll
    for (int i = 0; i < 4; i++)
        #pragma unroll
        for (int j = 0; j < 4; j++) acc[i][j] = 0.f;

    // stage 1: T = relu(Z @ Wa)
    {
        const float*  zb  = sZ + ty * 4 * 128;
        const float4* WaV = (const float4*)Wa;
        #pragma unroll 4
        for (int k = 0; k < 128; k++) {
            float a0 = zb[k];
            float a1 = zb[128 + k];
            float a2 = zb[256 + k];
            float a3 = zb[384 + k];
            float4 b = __ldg(WaV + k * 32 + tx);
            acc[0][0] = fmaf(a0, b.x, acc[0][0]); acc[0][1] = fmaf(a0, b.y, acc[0][1]);
            acc[0][2] = fmaf(a0, b.z, acc[0][2]); acc[0][3] = fmaf(a0, b.w, acc[0][3]);
            acc[1][0] = fmaf(a1, b.x, acc[1][0]); acc[1][1] = fmaf(a1, b.y, acc[1][1]);
            acc[1][2] = fmaf(a1, b.z, acc[1][2]); acc[1][3] = fmaf(a1, b.w, acc[1][3]);
            acc[2][0] = fmaf(a2, b.x, acc[2][0]); acc[2][1] = fmaf(a2, b.y, acc[2][1]);
            acc[2][2] = fmaf(a2, b.z, acc[2][2]); acc[2][3] = fmaf(a2, b.w, acc[2][3]);
            acc[3][0] = fmaf(a3, b.x, acc[3][0]); acc[3][1] = fmaf(a3, b.y, acc[3][1]);
            acc[3][2] = fmaf(a3, b.z, acc[3][2]); acc[3][3] = fmaf(a3, b.w, acc[3][3]);
        }
        #pragma unroll
        for (int i = 0; i < 4; i++) {
            float4 v;
            v.x = fmaxf(acc[i][0], 0.f);
            v.y = fmaxf(acc[i][1], 0.f);
            v.z = fmaxf(acc[i][2], 0.f);
            v.w = fmaxf(acc[i][3], 0.f);
            *(float4*)(sT + (ty * 4 + i) * 128 + tx * 4) = v;
            acc[i][0] = acc[i][1] = acc[i][2] = acc[i][3] = 0.f;
        }
    }
    __syncthreads();

    // stage 2: Out = act2(T @ Wb)
    {
        const float*  tb  = sT + ty * 4 * 128;
        const float4* WbV = (const float4*)Wb;
        #pragma unroll 4
        for (int k = 0; k < 128; k++) {
            float a0 = tb[k];
            float a1 = tb[128 + k];
            float a2 = tb[256 + k];
            float a3 = tb[384 + k];
            float4 b = __ldg(WbV + k * 32 + tx);
            acc[0][0] = fmaf(a0, b.x, acc[0][0]); acc[0][1] = fmaf(a0, b.y, acc[0][1]);
            acc[0][2] = fmaf(a0, b.z, acc[0][2]); acc[0][3] = fmaf(a0, b.w, acc[0][3]);
            acc[1][0] = fmaf(a1, b.x, acc[1][0]); acc[1][1] = fmaf(a1, b.y, acc[1][1]);
            acc[1][2] = fmaf(a1, b.z, acc[1][2]); acc[1][3] = fmaf(a1, b.w, acc[1][3]);
            acc[2][0] = fmaf(a2, b.x, acc[2][0]); acc[2][1] = fmaf(a2, b.y, acc[2][1]);
            acc[2][2] = fmaf(a2, b.z, acc[2][2]); acc[2][3] = fmaf(a2, b.w, acc[2][3]);
            acc[3][0] = fmaf(a3, b.x, acc[3][0]); acc[3][1] = fmaf(a3, b.y, acc[3][1]);
            acc[3][2] = fmaf(a3, b.z, acc[3][2]); acc[3][3] = fmaf(a3, b.w, acc[3][3]);
        }
    }

    float* Out = (LAYER == 1) ? g_bufB : OutExt;
    #pragma unroll
    for (int i = 0; i < 4; i++) {
        int row = row0 + ty * 4 + i;
        if (row < n) {
            float4 v;
            if (LAYER == 1) {   // relu between convs
                v.x = fmaxf(acc[i][0], 0.f); v.y = fmaxf(acc[i][1], 0.f);
                v.z = fmaxf(acc[i][2], 0.f); v.w = fmaxf(acc[i][3], 0.f);
            } else {
                v.x = acc[i][0]; v.y = acc[i][1]; v.z = acc[i][2]; v.w = acc[i][3];
            }
            ((float4*)(Out + (size_t)row * D))[tx] = v;
        }
    }
}

// ---------------- launch ----------------
extern "C" void kernel_launch(void* const* d_in, const int* in_sizes, int n_in,
                              void* d_out, int out_size) {
    float* out = (float*)d_out;

    // N comes from the OUTPUT size: exact, no identification needed.
    int N = out_size / D;
    if (N > NMAX) N = NMAX;
    if (N < 1)    N = 1;

    KArgs a;
    int m = n_in < 12 ? n_in : 12;
    for (int i = 0; i < 12; i++) { a.p[i] = 0; a.sz[i] = 0; }
    for (int i = 0; i < m; i++) {
        a.p[i]  = (unsigned long long)d_in[i];
        a.sz[i] = in_sizes[i];
    }
    a.n_in = m;
    a.N    = N;

    // Host-side E upper bound for grid sizing (device uses g_cfg.E for exact count):
    // max size <= EMAX that is not a weight (16384) and not x-sized.
    long long Eest = 0;
    for (int i = 0; i < m; i++) {
        long long s = in_sizes[i];
        if (s == 16384 || s == (long long)N * D) continue;
        if (s <= EMAX && s > Eest) Eest = s;
    }
    if (Eest <= 0) Eest = EMAX;

    k_config<<<1, 256>>>(a);
    k_zero_out<<<(int)((out_size + 255) / 256), 256>>>(out, (long long)out_size);

    const int prepGrid = (N * (D / 4) + 255) / 256;
    const int scatGrid = (int)((Eest * 32 + 255) / 256);
    const int mlpGrid  = (N + 31) / 32;

    // layer 1
    k_prep<true><<<prepGrid, 256>>>(N);
    k_scatter<true><<<scatGrid, 256>>>(N);
    k_mlp<1><<<mlpGrid, 256>>>(out, N);

    // layer 2
    k_prep<false><<<prepGrid, 256>>>(N);
    k_scatter<false><<<scatGrid, 256>>>(N);
    k_mlp<2><<<mlpGrid, 256>>>(out, N);
}

// round 8
// speedup vs baseline: 1.9608x; 1.9608x over previous
#include <cuda_runtime.h>

#define D     128
#define NMAX  50000
#define EMAX  800000
#define GIN_EPS 0.1f

// ---------------- device-resident configuration ----------------
struct Cfg {
    unsigned long long x;      // node features
    unsigned long long ei;     // edge_index
    unsigned long long ew;     // edge_weight
    unsigned long long w[4];   // W1a, W1b, W2a, W2b
    int E;
    int is64;
};
__device__ Cfg g_cfg;

__device__ int   g_deg[NMAX];
__device__ int   g_rowptr[NMAX + 1];
__device__ int   g_cursor[NMAX];
__device__ int   g_esrc[EMAX];
__device__ float g_ewt[EMAX];
__device__ __align__(16) float g_bufA[(size_t)NMAX * D];   // z (aggr output)
__device__ __align__(16) float g_bufB[(size_t)NMAX * D];   // h after layer 1

struct KArgs {
    unsigned long long p[12];
    long long          sz[12];
    int n_in;
    int N;
};

// ---------------- config kernel: classify inputs BY CONTENT (parallel scoring) ----------------
__global__ void k_config(KArgs a) {
    __shared__ int gs[12];   // "gaussian-like" score
    __shared__ int us[12];   // "[0,1]-like" score
    __shared__ int hz[12];   // 1 if all sampled odd int32 words are zero (int64 signature)
    const int tid = threadIdx.x;

    if (tid < 12) { gs[tid] = 0; us[tid] = 0; hz[tid] = 1; }
    __syncthreads();

    // parallel scoring: 256 samples per buffer
    for (int i = 0; i < a.n_in; i++) {
        long long s = a.sz[i];
        if (s <= 0) continue;
        const float* f = (const float*)a.p[i];
        long long idx = (long long)tid * (s - 1) / 255;
        float v = f[idx];
        bool fin = isfinite(v);
        if (fin && fabsf(v) > 1e-6f && fabsf(v) < 1e4f) atomicAdd(&gs[i], 1);
        if (fin && v >= 0.0f && v <= 1.0f)              atomicAdd(&us[i], 1);
        // int64 high-word test on first min(2048, s/2) pairs
        const int* w32 = (const int*)a.p[i];
        long long pairs = s / 2; if (pairs > 2048) pairs = 2048;
        for (long long k = tid; k < pairs; k += 256)
            if (w32[2 * k + 1] != 0) hz[i] = 0;
    }
    __syncthreads();

    if (tid != 0) return;

    Cfg c;
    bool used[12];
    for (int i = 0; i < 12; i++) used[i] = (i >= a.n_in);

    // 1) weights: exactly 16384 elements, in index order
    int nw = 0;
    for (int i = 0; i < a.n_in; i++)
        if (!used[i] && a.sz[i] == 16384 && nw < 4) { c.w[nw++] = a.p[i]; used[i] = true; }
    while (nw < 4) c.w[nw++] = a.p[0];

    // 2) x: size == N*128 with best gaussian score
    long long xneed = (long long)a.N * 128;
    int xi = -1, best = -1;
    for (int i = 0; i < a.n_in; i++)
        if (!used[i] && a.sz[i] == xneed && gs[i] > best) { best = gs[i]; xi = i; }
    if (xi < 0) {
        long long b = -1;
        for (int i = 0; i < a.n_in; i++)
            if (!used[i] && a.sz[i] > b) { b = a.sz[i]; xi = i; }
        if (xi < 0) xi = 0;
    }
    c.x = a.p[xi]; used[xi] = true;

    // 3) edge_weight: size in (0, EMAX], best [0,1] score
    int ewi = -1; best = -1;
    for (int i = 0; i < a.n_in; i++) {
        if (used[i]) continue;
        long long s = a.sz[i];
        if (s < 1 || s > EMAX) continue;
        if (us[i] > best) { best = us[i]; ewi = i; }
    }
    if (ewi < 0) {
        long long b = (long long)1 << 62;
        for (int i = 0; i < a.n_in; i++)
            if (!used[i] && a.sz[i] < b) { b = a.sz[i]; ewi = i; }
        if (ewi < 0) ewi = 0;
    }
    c.ew = a.p[ewi]; used[ewi] = true;
    long long Ell = a.sz[ewi];
    c.E = (int)(Ell > EMAX ? EMAX : Ell);

    // 4) edge_index: remaining largest
    int eii = -1; long long b2 = -1;
    for (int i = 0; i < a.n_in; i++)
        if (!used[i] && a.sz[i] > b2) { b2 = a.sz[i]; eii = i; }
    if (eii < 0) eii = ewi;
    c.ei = a.p[eii];
    c.is64 = hz[eii];

    g_cfg = c;
}

// ---------------- helpers ----------------
__device__ __forceinline__ int load_idx(size_t pos) {
    if (g_cfg.is64) return (int)((const long long*)g_cfg.ei)[pos];
    return ((const int*)g_cfg.ei)[pos];
}

// ---------------- zero CSR counters ----------------
__global__ void k_zero_csr(int n) {
    int i = blockIdx.x * blockDim.x + threadIdx.x;
    if (i < n) { g_deg[i] = 0; g_cursor[i] = 0; }
}

// ---------------- zero output (covers any rows beyond N) ----------------
__global__ void k_zero_out(float* out, long long n) {
    long long i = (long long)blockIdx.x * blockDim.x + threadIdx.x;
    if (i < n) out[i] = 0.0f;
}

// ---------------- CSR build ----------------
__global__ void k_hist(int n) {
    int e = blockIdx.x * blockDim.x + threadIdx.x;
    int E = g_cfg.E;
    if (e < E) {
        int d = load_idx((size_t)E + e);
        if ((unsigned)d < (unsigned)n) atomicAdd(&g_deg[d], 1);
    }
}

// single-block exclusive scan of g_deg[0..n) -> g_rowptr, plus g_rowptr[n]=total
__global__ void k_scan(int n) {
    __shared__ int warp_sums[32];
    __shared__ int s_carry;
    if (threadIdx.x == 0) s_carry = 0;
    __syncthreads();
    int lane = threadIdx.x & 31;
    int wid  = threadIdx.x >> 5;
    for (int base = 0; base < n; base += 1024) {
        int i = base + (int)threadIdx.x;
        int v = (i < n) ? g_deg[i] : 0;
        int x = v;
        #pragma unroll
        for (int o = 1; o < 32; o <<= 1) {
            int t = __shfl_up_sync(0xFFFFFFFFu, x, o);
            if (lane >= o) x += t;
        }
        if (lane == 31) warp_sums[wid] = x;
        __syncthreads();
        if (wid == 0) {
            int w = warp_sums[lane];
            #pragma unroll
            for (int o = 1; o < 32; o <<= 1) {
                int t = __shfl_up_sync(0xFFFFFFFFu, w, o);
                if (lane >= o) w += t;
            }
            warp_sums[lane] = w;
        }
        __syncthreads();
        int incl  = x + (wid ? warp_sums[wid - 1] : 0);
        int carry = s_carry;
        if (i < n) g_rowptr[i] = carry + incl - v;   // exclusive
        __syncthreads();
        if (threadIdx.x == 1023) s_carry = carry + incl;
        __syncthreads();
    }
    if (threadIdx.x == 0) g_rowptr[n] = s_carry;
}

__global__ void k_fill(int n) {
    int e = blockIdx.x * blockDim.x + threadIdx.x;
    int E = g_cfg.E;
    if (e < E) {
        int d = load_idx((size_t)E + e);
        int s = load_idx(e);
        if ((unsigned)d < (unsigned)n && (unsigned)s < (unsigned)n) {
            int p = g_rowptr[d] + atomicAdd(&g_cursor[d], 1);
            g_esrc[p] = s;
            g_ewt[p]  = ((const float*)g_cfg.ew)[e];
        }
    }
}

// ---------------- aggregation (gather): z[i] = (1+eps)*h[i] + sum_{j->i} w*h[j] ----------------
// one warp per node, float4 per lane. FIRST: h = x, else h = g_bufB. writes g_bufA.
template <bool FIRST>
__global__ void k_aggr(int n) {
    int t    = blockIdx.x * blockDim.x + threadIdx.x;
    int node = t >> 5;
    int lane = t & 31;
    if (node >= n) return;

    const float* h = FIRST ? (const float*)g_cfg.x : g_bufB;

    float4 acc = ((const float4*)(h + (size_t)node * D))[lane];
    acc.x *= (1.0f + GIN_EPS);
    acc.y *= (1.0f + GIN_EPS);
    acc.z *= (1.0f + GIN_EPS);
    acc.w *= (1.0f + GIN_EPS);

    int k0 = g_rowptr[node], k1 = g_rowptr[node + 1];
    int k = k0;
    int   s_nxt = 0; float w_nxt = 0.0f;
    if (k < k1) { s_nxt = g_esrc[k]; w_nxt = g_ewt[k]; }
    while (k < k1) {
        int s = s_nxt; float w = w_nxt;
        int k2 = k + 1;
        if (k2 < k1) { s_nxt = g_esrc[k2]; w_nxt = g_ewt[k2]; }
        float4 v = ((const float4*)(h + (size_t)s * D))[lane];
        acc.x = fmaf(w, v.x, acc.x);
        acc.y = fmaf(w, v.y, acc.y);
        acc.z = fmaf(w, v.z, acc.z);
        acc.w = fmaf(w, v.w, acc.w);
        k = k2;
    }
    ((float4*)(g_bufA + (size_t)node * D))[lane] = acc;
}

// ---------------- fused 2-layer MLP: Out = act2( relu(Z @ Wa) @ Wb ) ----------------
// 32 KB static smem; weights via __ldg (hot in L1). 256 thr = 8 warps;
// tile 32 rows x 128 cols; 4x4 micro-tile per thread.
template <int LAYER>
__global__ void k_mlp(float* __restrict__ OutExt, int n) {
    __shared__ __align__(16) float sZ[32 * 128];
    __shared__ __align__(16) float sT[32 * 128];

    const float* Wa = (const float*)(LAYER == 1 ? g_cfg.w[0] : g_cfg.w[2]);
    const float* Wb = (const float*)(LAYER == 1 ? g_cfg.w[1] : g_cfg.w[3]);

    const int tid  = threadIdx.x;
    const int row0 = blockIdx.x * 32;

    {
        float4* dz = (float4*)sZ;
        for (int i = tid; i < 1024; i += 256) {
            int r  = i >> 5;
            int cc = i & 31;
            int gr = row0 + r;
            float4 v = make_float4(0.f, 0.f, 0.f, 0.f);
            if (gr < n) v = ((const float4*)(g_bufA + (size_t)gr * D))[cc];
            dz[i] = v;
        }
    }
    __syncthreads();

    const int tx = tid & 31;
    const int ty = tid >> 5;

    float acc[4][4];
    #pragma unroll
    for (int i = 0; i < 4; i++)
        #pragma unroll
        for (int j = 0; j < 4; j++) acc[i][j] = 0.f;

    // stage 1: T = relu(Z @ Wa)
    {
        const float*  zb  = sZ + ty * 4 * 128;
        const float4* WaV = (const float4*)Wa;
        #pragma unroll 4
        for (int k = 0; k < 128; k++) {
            float a0 = zb[k];
            float a1 = zb[128 + k];
            float a2 = zb[256 + k];
            float a3 = zb[384 + k];
            float4 b = __ldg(WaV + k * 32 + tx);
            acc[0][0] = fmaf(a0, b.x, acc[0][0]); acc[0][1] = fmaf(a0, b.y, acc[0][1]);
            acc[0][2] = fmaf(a0, b.z, acc[0][2]); acc[0][3] = fmaf(a0, b.w, acc[0][3]);
            acc[1][0] = fmaf(a1, b.x, acc[1][0]); acc[1][1] = fmaf(a1, b.y, acc[1][1]);
            acc[1][2] = fmaf(a1, b.z, acc[1][2]); acc[1][3] = fmaf(a1, b.w, acc[1][3]);
            acc[2][0] = fmaf(a2, b.x, acc[2][0]); acc[2][1] = fmaf(a2, b.y, acc[2][1]);
            acc[2][2] = fmaf(a2, b.z, acc[2][2]); acc[2][3] = fmaf(a2, b.w, acc[2][3]);
            acc[3][0] = fmaf(a3, b.x, acc[3][0]); acc[3][1] = fmaf(a3, b.y, acc[3][1]);
            acc[3][2] = fmaf(a3, b.z, acc[3][2]); acc[3][3] = fmaf(a3, b.w, acc[3][3]);
        }
        #pragma unroll
        for (int i = 0; i < 4; i++) {
            float4 v;
            v.x = fmaxf(acc[i][0], 0.f);
            v.y = fmaxf(acc[i][1], 0.f);
            v.z = fmaxf(acc[i][2], 0.f);
            v.w = fmaxf(acc[i][3], 0.f);
            *(float4*)(sT + (ty * 4 + i) * 128 + tx * 4) = v;
            acc[i][0] = acc[i][1] = acc[i][2] = acc[i][3] = 0.f;
        }
    }
    __syncthreads();

    // stage 2: Out = act2(T @ Wb)
    {
        const float*  tb  = sT + ty * 4 * 128;
        const float4* WbV = (const float4*)Wb;
        #pragma unroll 4
        for (int k = 0; k < 128; k++) {
            float a0 = tb[k];
            float a1 = tb[128 + k];
            float a2 = tb[256 + k];
            float a3 = tb[384 + k];
            float4 b = __ldg(WbV + k * 32 + tx);
            acc[0][0] = fmaf(a0, b.x, acc[0][0]); acc[0][1] = fmaf(a0, b.y, acc[0][1]);
            acc[0][2] = fmaf(a0, b.z, acc[0][2]); acc[0][3] = fmaf(a0, b.w, acc[0][3]);
            acc[1][0] = fmaf(a1, b.x, acc[1][0]); acc[1][1] = fmaf(a1, b.y, acc[1][1]);
            acc[1][2] = fmaf(a1, b.z, acc[1][2]); acc[1][3] = fmaf(a1, b.w, acc[1][3]);
            acc[2][0] = fmaf(a2, b.x, acc[2][0]); acc[2][1] = fmaf(a2, b.y, acc[2][1]);
            acc[2][2] = fmaf(a2, b.z, acc[2][2]); acc[2][3] = fmaf(a2, b.w, acc[2][3]);
            acc[3][0] = fmaf(a3, b.x, acc[3][0]); acc[3][1] = fmaf(a3, b.y, acc[3][1]);
            acc[3][2] = fmaf(a3, b.z, acc[3][2]); acc[3][3] = fmaf(a3, b.w, acc[3][3]);
        }
    }

    float* Out = (LAYER == 1) ? g_bufB : OutExt;
    #pragma unroll
    for (int i = 0; i < 4; i++) {
        int row = row0 + ty * 4 + i;
        if (row < n) {
            float4 v;
            if (LAYER == 1) {
                v.x = fmaxf(acc[i][0], 0.f); v.y = fmaxf(acc[i][1], 0.f);
                v.z = fmaxf(acc[i][2], 0.f); v.w = fmaxf(acc[i][3], 0.f);
            } else {
                v.x = acc[i][0]; v.y = acc[i][1]; v.z = acc[i][2]; v.w = acc[i][3];
            }
            ((float4*)(Out + (size_t)row * D))[tx] = v;
        }
    }
}

// ---------------- launch ----------------
extern "C" void kernel_launch(void* const* d_in, const int* in_sizes, int n_in,
                              void* d_out, int out_size) {
    float* out = (float*)d_out;

    int N = out_size / D;
    if (N > NMAX) N = NMAX;
    if (N < 1)    N = 1;

    KArgs a;
    int m = n_in < 12 ? n_in : 12;
    for (int i = 0; i < 12; i++) { a.p[i] = 0; a.sz[i] = 0; }
    for (int i = 0; i < m; i++) {
        a.p[i]  = (unsigned long long)d_in[i];
        a.sz[i] = in_sizes[i];
    }
    a.n_in = m;
    a.N    = N;

    // Host-side E upper bound for grid sizing (device uses g_cfg.E exactly).
    long long Eest = 0;
    for (int i = 0; i < m; i++) {
        long long s = in_sizes[i];
        if (s == 16384 || s == (long long)N * D) continue;
        if (s <= EMAX && s > Eest) Eest = s;
    }
    if (Eest <= 0) Eest = EMAX;

    const int edgeGrid = (int)((Eest + 255) / 256);
    const int aggrGrid = (N * 32 + 255) / 256;
    const int mlpGrid  = (N + 31) / 32;

    k_config<<<1, 256>>>(a);
    k_zero_csr<<<(N + 255) / 256, 256>>>(N);
    k_zero_out<<<(int)((out_size + 255) / 256), 256>>>(out, (long long)out_size);

    // CSR build (shared by both layers)
    k_hist<<<edgeGrid, 256>>>(N);
    k_scan<<<1, 1024>>>(N);
    k_fill<<<edgeGrid, 256>>>(N);

    // layer 1
    k_aggr<true><<<aggrGrid, 256>>>(N);
    k_mlp<1><<<mlpGrid, 256>>>(out, N);

    // layer 2
    k_aggr<false><<<aggrGrid, 256>>>(N);
    k_mlp<2><<<mlpGrid, 256>>>(out, N);
}